// round 8
// baseline (speedup 1.0000x reference)
#include <cuda_runtime.h>
#include <math.h>

constexpr int Bn   = 64;
constexpr int Hn   = 512;
constexpr int Wn   = 512;
constexpr int NPTS = 512;
constexpr int HWn  = Hn * Wn;
constexpr int SLICES = 16;                  // blocks per image
constexpr int RB = Bn * SLICES;             // 1024 blocks (single wave @occ7)
constexpr int TAPS_PER_IMG = NPTS * 9;      // 4608
constexpr int TAPS_PER_BLK = TAPS_PER_IMG / SLICES;   // 288
constexpr int NTAP = Bn * TAPS_PER_IMG;     // 294912
constexpr int CB = NTAP / 256;              // 1152 cleanup blocks (per-tap)
constexpr float SCALE = 0.25f;              // 512/2048
constexpr double CELL_AREA = 16.0;

// zero-initialized device scratch; restored every call for graph replay
__device__ float  g_target[(size_t)Bn * HWn];
__device__ double g_S[Bn], g_Q[Bn], g_T[Bn], g_A[Bn], g_C[Bn];

// K1: each block streams its slice of pred (S,Q) then processes the 288 taps
//     of the same image chunk (scatter + T + A + C via atomic telescoping).
__global__ void __launch_bounds__(256, 7)
k_main(const float* __restrict__ pred, const float* __restrict__ points) {
    const int tid = threadIdx.x;
    const int b = blockIdx.x >> 4;
    const int slice = blockIdx.x & (SLICES - 1);

    // ---- streaming part: 16 float4 per thread, batched 8-deep ----
    constexpr int CH = HWn / 4 / SLICES;    // 4096 float4 per block
    const float4* p = reinterpret_cast<const float4*>(pred)
                      + (size_t)b * (HWn / 4) + (size_t)slice * CH;
    float s = 0.f, q = 0.f;
    #pragma unroll
    for (int it = 0; it < 2; ++it) {
        float4 v[8];
        #pragma unroll
        for (int j = 0; j < 8; ++j)
            v[j] = p[(it * 8 + j) * 256 + tid];
        #pragma unroll
        for (int j = 0; j < 8; ++j) {
            s += (v[j].x + v[j].y) + (v[j].z + v[j].w);
            q += v[j].x * v[j].x + v[j].y * v[j].y
               + v[j].z * v[j].z + v[j].w * v[j].w;
        }
    }

    // ---- tap part: 288 taps of image b, chunk 'slice' ----
    float tw = 0.f, ta = 0.f, tc = 0.f;
    const float* pb = pred + (size_t)b * HWn;
    float* tg = g_target + (size_t)b * HWn;
    for (int i = tid; i < TAPS_PER_BLK; i += 256) {
        int tapid = slice * TAPS_PER_BLK + i;    // < 4608
        int pt  = tapid / 9;
        int tap = tapid - pt * 9;
        float px = __ldg(&points[((size_t)b * NPTS + pt) * 2 + 0]);
        float py = __ldg(&points[((size_t)b * NPTS + pt) * 2 + 1]);
        int x = (int)fminf(fmaxf(px * SCALE, 0.f), (float)(Wn - 1));
        int y = (int)fminf(fmaxf(py * SCALE, 0.f), (float)(Hn - 1));
        int dy = tap / 3 - 1;
        int dx = tap - (tap / 3) * 3 - 1;
        int ny = y + dy, nx = x + dx;
        if ((unsigned)ny < (unsigned)Hn && (unsigned)nx < (unsigned)Wn) {
            int r2 = dy * dy + dx * dx;
            float w = (r2 == 0) ? 1.0f : (r2 == 1 ? 0.60653066f : 0.49306869f);
            int idx = ny * Wn + nx;
            float old = atomicAdd(&tg[idx], w);   // returning atomic
            tc += w * (2.f * old + w);            // (old+w)^2 - old^2
            ta += w * __ldg(&pb[idx]);            // L2-warm (image streaming now)
            tw += w;
        }
    }

    // ---- block reduce all five accumulators; whole block shares b ----
    #pragma unroll
    for (int o = 16; o; o >>= 1) {
        s  += __shfl_down_sync(0xffffffffu, s,  o);
        q  += __shfl_down_sync(0xffffffffu, q,  o);
        tw += __shfl_down_sync(0xffffffffu, tw, o);
        ta += __shfl_down_sync(0xffffffffu, ta, o);
        tc += __shfl_down_sync(0xffffffffu, tc, o);
    }
    __shared__ float sh[5][8];
    int lane = tid & 31, wid = tid >> 5;
    if (lane == 0) {
        sh[0][wid] = s; sh[1][wid] = q; sh[2][wid] = tw;
        sh[3][wid] = ta; sh[4][wid] = tc;
    }
    __syncthreads();
    if (wid == 0) {
        s  = (lane < 8) ? sh[0][lane] : 0.f;
        q  = (lane < 8) ? sh[1][lane] : 0.f;
        tw = (lane < 8) ? sh[2][lane] : 0.f;
        ta = (lane < 8) ? sh[3][lane] : 0.f;
        tc = (lane < 8) ? sh[4][lane] : 0.f;
        #pragma unroll
        for (int o = 4; o; o >>= 1) {
            s  += __shfl_down_sync(0xffffffffu, s,  o);
            q  += __shfl_down_sync(0xffffffffu, q,  o);
            tw += __shfl_down_sync(0xffffffffu, tw, o);
            ta += __shfl_down_sync(0xffffffffu, ta, o);
            tc += __shfl_down_sync(0xffffffffu, tc, o);
        }
        if (lane == 0) {
            atomicAdd(&g_S[b], (double)s);
            atomicAdd(&g_Q[b], (double)q);
            atomicAdd(&g_T[b], (double)tw);
            atomicAdd(&g_A[b], (double)ta);
            atomicAdd(&g_C[b], (double)tc);
        }
    }
}

// K2: blocks [0,CB) zero touched cells, one TAP per thread (plain stores);
//     block CB finalizes (stream-ordered after K1).
__global__ void __launch_bounds__(256)
k_tail(const float* __restrict__ points, float* __restrict__ out) {
    const int tid = threadIdx.x;
    if (blockIdx.x < CB) {
        int u = blockIdx.x * 256 + tid;
        int pt  = u / 9;
        int tap = u - pt * 9;
        int b = pt >> 9;
        float px = __ldg(&points[2 * pt + 0]);
        float py = __ldg(&points[2 * pt + 1]);
        int x = (int)fminf(fmaxf(px * SCALE, 0.f), (float)(Wn - 1));
        int y = (int)fminf(fmaxf(py * SCALE, 0.f), (float)(Hn - 1));
        int dy = tap / 3 - 1;
        int dx = tap - (tap / 3) * 3 - 1;
        int ny = y + dy, nx = x + dx;
        if ((unsigned)ny < (unsigned)Hn && (unsigned)nx < (unsigned)Wn)
            g_target[(size_t)b * HWn + ny * Wn + nx] = 0.f;
        return;
    }

    // finalize block
    double cnt = 0.0, sp = 0.0;
    if (tid < Bn) {
        double S = g_S[tid];
        cnt = fabs(S / CELL_AREA - (double)NPTS);
        double Sp = S + 1e-8;
        double T = g_T[tid];
        sp = (g_Q[tid] / (Sp * Sp) - 2.0 * g_A[tid] / (Sp * T) + g_C[tid] / (T * T))
             / (double)HWn;
        g_S[tid] = 0.0; g_Q[tid] = 0.0; g_T[tid] = 0.0;
        g_A[tid] = 0.0; g_C[tid] = 0.0;
    }
    #pragma unroll
    for (int o = 16; o; o >>= 1) {
        cnt += __shfl_down_sync(0xffffffffu, cnt, o);
        sp  += __shfl_down_sync(0xffffffffu, sp, o);
    }
    __shared__ double sc[2], ssp[2];
    int lane = tid & 31, wid = tid >> 5;
    if (wid < 2 && lane == 0) { sc[wid] = cnt; ssp[wid] = sp; }
    __syncthreads();
    if (tid == 0) {
        double count_loss = (sc[0] + sc[1]) / (double)Bn;
        double spatial    = (ssp[0] + ssp[1]) / (double)Bn;
        out[0] = (float)(2.5 * count_loss + 0.1 * spatial);
        out[1] = (float)count_loss;
        out[2] = (float)spatial;
    }
}

extern "C" void kernel_launch(void* const* d_in, const int* in_sizes, int n_in,
                              void* d_out, int out_size) {
    const float* pred   = (const float*)d_in[0];
    const float* points = (const float*)d_in[1];
    float* out = (float*)d_out;
    k_main<<<RB, 256>>>(pred, points);
    k_tail<<<CB + 1, 256>>>(points, out);
}